// round 6
// baseline (speedup 1.0000x reference)
#include <cuda_runtime.h>
#include <cstddef>

#define BB 256
#define TT 2048
#define NXX 64
#define NUU 32
#define NYY 16
#define HH 128

// IEEE round-to-nearest divide, immune to fast-math substitution.
__device__ __forceinline__ float fdiv_rn(float a, float b) {
    float r; asm("div.rn.f32 %0, %1, %2;" : "=f"(r) : "f"(a), "f"(b)); return r;
}

// Exact replication of XLA EmitFastTanh (FMA-capable target):
// clamp to +-7.99881172180175781, rational poly (deg-13 odd / deg-6 even),
// IEEE div, |x|<4e-4 -> x. All muls pinned with __fmul_rn so unsafe-math
// cannot reassociate; fmaf chain matches XLA's fma lowering.
__device__ __forceinline__ float xla_tanh(float x) {
    const float kClamp = 7.99881172180175781f;
    float xc = fmaxf(-kClamp, fminf(x, kClamp));
    float x2 = __fmul_rn(xc, xc);
    float p = fmaf(x2, -2.76076847742355e-16f, 2.00018790482477e-13f); // a13,a11
    p = fmaf(x2, p, -8.60467152213735e-11f);  // a9
    p = fmaf(x2, p,  5.12229709037114e-08f);  // a7
    p = fmaf(x2, p,  1.48572235717979e-05f);  // a5
    p = fmaf(x2, p,  6.37261928875436e-04f);  // a3
    p = fmaf(x2, p,  4.89352455891786e-03f);  // a1
    float num = __fmul_rn(xc, p);
    float q = fmaf(x2, 1.19825839466702e-06f, 1.18534705686654e-04f);  // b6,b4
    q = fmaf(x2, q, 2.26843463243900e-03f);   // b2
    q = fmaf(x2, q, 4.89352518554385e-03f);   // b0
    float r = fdiv_rn(num, q);
    return (fabsf(x) < 0.0004f) ? x : r;
}

// 128 CTAs x 288 threads; 2 batch elements per CTA.
// tid   0..127 : GEMV1 (layer-1 of g and h), one H-column each, weights in regs.
// tid 128..255 : dx threads — one (e,j) each, full 128-long sequential dot.
// tid 256..287 : y  threads — one (e,o) each, full 128-long sequential dot.
// Every dot: single fp32 accumulator, k ascending. All order-sensitive adds
// pinned with __fadd_rn; residual update in HLO source order x + (dot + b).

__global__ __launch_bounds__(288, 1)
void ssm_kernel(const float* __restrict__ x0,
                const float* __restrict__ u,
                const float* __restrict__ Wg1, const float* __restrict__ bg1,
                const float* __restrict__ Wg2, const float* __restrict__ bg2,
                const float* __restrict__ Wh1, const float* __restrict__ bh1,
                const float* __restrict__ Wh2, const float* __restrict__ bh2,
                float* __restrict__ out_x, float* __restrict__ out_y)
{
    __shared__ __align__(16) float sx[2][NXX];   // exact x_t
    __shared__ __align__(16) float su[2][NUU];   // u_t
    __shared__ __align__(16) float g1s[2][HH];   // tanh(g layer-1)
    __shared__ __align__(16) float h1s[2][HH];   // tanh(h layer-1)

    const int tid = threadIdx.x;
    const int b0  = blockIdx.x * 2;

    // ---- init state & u_0 ----
    if (tid < 128) {
        int e = tid >> 6, j = tid & 63;
        sx[e][j] = x0[(size_t)(b0 + e) * NXX + j];
    } else if (tid < 192) {
        int q = tid - 128;
        int e = q >> 5, k = q & 31;
        su[e][k] = u[(size_t)(b0 + e) * TT * NUU + k];
    }

    if (tid < 128) {
        // ===================== GEMV1 =====================
        const int h = tid;
        float wg1r[96];
        float wh1r[64];
        #pragma unroll
        for (int k = 0; k < 96; k++) wg1r[k] = Wg1[k * HH + h];
        #pragma unroll
        for (int k = 0; k < 64; k++) wh1r[k] = Wh1[k * HH + h];
        const float bg1r = bg1[h];
        const float bh1r = bh1[h];

        __syncthreads();  // init visible

        const float4* x40 = (const float4*)&sx[0][0];
        const float4* x41 = (const float4*)&sx[1][0];
        const float4* u40 = (const float4*)&su[0][0];
        const float4* u41 = (const float4*)&su[1][0];

        for (int t = 0; t < TT; t++) {
            float zg0 = 0.f, zg1 = 0.f, zh0 = 0.f, zh1 = 0.f;
            #pragma unroll
            for (int k4 = 0; k4 < 16; k4++) {
                const float4 a = x40[k4];
                const float4 b = x41[k4];
                zg0 = fmaf(a.x, wg1r[4*k4+0], zg0);
                zg0 = fmaf(a.y, wg1r[4*k4+1], zg0);
                zg0 = fmaf(a.z, wg1r[4*k4+2], zg0);
                zg0 = fmaf(a.w, wg1r[4*k4+3], zg0);
                zg1 = fmaf(b.x, wg1r[4*k4+0], zg1);
                zg1 = fmaf(b.y, wg1r[4*k4+1], zg1);
                zg1 = fmaf(b.z, wg1r[4*k4+2], zg1);
                zg1 = fmaf(b.w, wg1r[4*k4+3], zg1);
                zh0 = fmaf(a.x, wh1r[4*k4+0], zh0);
                zh0 = fmaf(a.y, wh1r[4*k4+1], zh0);
                zh0 = fmaf(a.z, wh1r[4*k4+2], zh0);
                zh0 = fmaf(a.w, wh1r[4*k4+3], zh0);
                zh1 = fmaf(b.x, wh1r[4*k4+0], zh1);
                zh1 = fmaf(b.y, wh1r[4*k4+1], zh1);
                zh1 = fmaf(b.z, wh1r[4*k4+2], zh1);
                zh1 = fmaf(b.w, wh1r[4*k4+3], zh1);
            }
            #pragma unroll
            for (int k4 = 0; k4 < 8; k4++) {
                const float4 a = u40[k4];
                const float4 b = u41[k4];
                zg0 = fmaf(a.x, wg1r[64+4*k4+0], zg0);
                zg0 = fmaf(a.y, wg1r[64+4*k4+1], zg0);
                zg0 = fmaf(a.z, wg1r[64+4*k4+2], zg0);
                zg0 = fmaf(a.w, wg1r[64+4*k4+3], zg0);
                zg1 = fmaf(b.x, wg1r[64+4*k4+0], zg1);
                zg1 = fmaf(b.y, wg1r[64+4*k4+1], zg1);
                zg1 = fmaf(b.z, wg1r[64+4*k4+2], zg1);
                zg1 = fmaf(b.w, wg1r[64+4*k4+3], zg1);
            }
            g1s[0][h] = xla_tanh(__fadd_rn(zg0, bg1r));
            g1s[1][h] = xla_tanh(__fadd_rn(zg1, bg1r));
            h1s[0][h] = xla_tanh(__fadd_rn(zh0, bh1r));
            h1s[1][h] = xla_tanh(__fadd_rn(zh1, bh1r));
            __syncthreads();  // A: g1/h1 published; all sx/su reads done
            __syncthreads();  // B: state/u updated by dx threads
        }
    } else if (tid < 256) {
        // ===================== dx threads =====================
        const int q = tid - 128;
        const int e = q >> 6;
        const int j = q & 63;

        float wg2r[128];
        #pragma unroll
        for (int i = 0; i < 128; i++) wg2r[i] = Wg2[i * NXX + j];
        const float bg2r = bg2[j];

        const size_t ox_base = (size_t)(b0 + e) * TT * NXX + j;
        const int eu = q >> 5, ku = q & 31;              // u prefetch duty (q<64)
        const size_t u_base = (size_t)(b0 + eu) * TT * NUU + ku;

        __syncthreads();  // init visible

        const float4* g4 = (const float4*)&g1s[e][0];

        for (int t = 0; t < TT; t++) {
            // record x_t (pre-update), prefetch u_{t+1}
            float xcur = sx[e][j];
            out_x[ox_base + (size_t)t * NXX] = xcur;
            float un = 0.0f;
            if (q < 64) {
                int tn = (t + 1 < TT) ? (t + 1) : (TT - 1);
                un = u[u_base + (size_t)tn * NUU];
            }
            __syncthreads();  // A

            float dxa = 0.0f;
            #pragma unroll
            for (int i4 = 0; i4 < 32; i4++) {
                const float4 v = g4[i4];
                dxa = fmaf(v.x, wg2r[4*i4+0], dxa);
                dxa = fmaf(v.y, wg2r[4*i4+1], dxa);
                dxa = fmaf(v.z, wg2r[4*i4+2], dxa);
                dxa = fmaf(v.w, wg2r[4*i4+3], dxa);
            }
            // HLO order, pinned: x_next = x + (dot + bg2)
            sx[e][j] = __fadd_rn(xcur, __fadd_rn(dxa, bg2r));
            if (q < 64) su[eu][ku] = un;
            __syncthreads();  // B
        }
    } else {
        // ===================== y threads =====================
        const int o  = tid - 256;       // 0..31
        const int e  = o >> 4;
        const int oo = o & 15;

        float wh2r[128];
        #pragma unroll
        for (int i = 0; i < 128; i++) wh2r[i] = Wh2[i * NYY + oo];
        const float bh2r = bh2[oo];

        const size_t oy_base = (size_t)(b0 + e) * TT * NYY + oo;

        __syncthreads();  // init visible

        const float4* h4 = (const float4*)&h1s[e][0];

        for (int t = 0; t < TT; t++) {
            __syncthreads();  // A

            float ya = 0.0f;
            #pragma unroll
            for (int i4 = 0; i4 < 32; i4++) {
                const float4 v = h4[i4];
                ya = fmaf(v.x, wh2r[4*i4+0], ya);
                ya = fmaf(v.y, wh2r[4*i4+1], ya);
                ya = fmaf(v.z, wh2r[4*i4+2], ya);
                ya = fmaf(v.w, wh2r[4*i4+3], ya);
            }
            out_y[oy_base + (size_t)t * NYY] = __fadd_rn(ya, bh2r);
            __syncthreads();  // B
        }
    }
}

extern "C" void kernel_launch(void* const* d_in, const int* in_sizes, int n_in,
                              void* d_out, int out_size)
{
    const float* x0  = (const float*)d_in[0];
    const float* u   = (const float*)d_in[1];
    const float* Wg1 = (const float*)d_in[2];
    const float* bg1 = (const float*)d_in[3];
    const float* Wg2 = (const float*)d_in[4];
    const float* bg2 = (const float*)d_in[5];
    const float* Wh1 = (const float*)d_in[6];
    const float* bh1 = (const float*)d_in[7];
    const float* Wh2 = (const float*)d_in[8];
    const float* bh2 = (const float*)d_in[9];

    float* out_x = (float*)d_out;
    float* out_y = out_x + (size_t)BB * TT * NXX;

    ssm_kernel<<<BB / 2, 288>>>(x0, u, Wg1, bg1, Wg2, bg2,
                                Wh1, bh1, Wh2, bh2, out_x, out_y);
}

// round 7
// speedup vs baseline: 1.0372x; 1.0372x over previous
#include <cuda_runtime.h>
#include <cstddef>

#define BB 256
#define TT 2048
#define NXX 64
#define NUU 32
#define NYY 16
#define HH 128

// IEEE round-to-nearest divide, immune to fast-math substitution.
__device__ __forceinline__ float fdiv_rn(float a, float b) {
    float r; asm("div.rn.f32 %0, %1, %2;" : "=f"(r) : "f"(a), "f"(b)); return r;
}

// Exact replication of XLA EmitFastTanh (FMA-capable target). DO NOT TOUCH.
__device__ __forceinline__ float xla_tanh(float x) {
    const float kClamp = 7.99881172180175781f;
    float xc = fmaxf(-kClamp, fminf(x, kClamp));
    float x2 = __fmul_rn(xc, xc);
    float p = fmaf(x2, -2.76076847742355e-16f, 2.00018790482477e-13f);
    p = fmaf(x2, p, -8.60467152213735e-11f);
    p = fmaf(x2, p,  5.12229709037114e-08f);
    p = fmaf(x2, p,  1.48572235717979e-05f);
    p = fmaf(x2, p,  6.37261928875436e-04f);
    p = fmaf(x2, p,  4.89352455891786e-03f);
    float num = __fmul_rn(xc, p);
    float q = fmaf(x2, 1.19825839466702e-06f, 1.18534705686654e-04f);
    q = fmaf(x2, q, 2.26843463243900e-03f);
    q = fmaf(x2, q, 4.89352518554385e-03f);
    float r = fdiv_rn(num, q);
    return (fabsf(x) < 0.0004f) ? x : r;
}

// 128 CTAs x 288 threads; 2 batch elements per CTA.
//   tid   0..127 : GEMV1. Phase 1: zg chains (k=0..95 ascending) -> g1s.
//                  Phase 2: zh chains (k=0..63) -> h1p (overlaps dx chain).
//   tid 128..255 : dx threads, one (e,j) each. Phase 1: out_x store + u LDG.
//                  Phase 2: 128-long sequential dot (ascending), state update.
//   tid 256..287 : y threads, one (e,o) each: compute y(t-1) during phase 1
//                  (one step behind, double-buffered h1), drained after loop.
// All dots: single fp32 accumulator, k ascending; adds pinned with __fadd_rn.
// Arithmetic is bit-identical to the R6 kernel — only the schedule changed.

__global__ __launch_bounds__(288, 1)
void ssm_kernel(const float* __restrict__ x0,
                const float* __restrict__ u,
                const float* __restrict__ Wg1, const float* __restrict__ bg1,
                const float* __restrict__ Wg2, const float* __restrict__ bg2,
                const float* __restrict__ Wh1, const float* __restrict__ bh1,
                const float* __restrict__ Wh2, const float* __restrict__ bh2,
                float* __restrict__ out_x, float* __restrict__ out_y)
{
    __shared__ __align__(16) float sxu[2][2][96];   // [parity][e][0..63 x | 64..95 u]
    __shared__ __align__(16) float g1s[2][HH];      // tanh(g layer-1), single buffer
    __shared__ __align__(16) float h1p[2][2][HH];   // tanh(h layer-1), double buffer

    const int tid = threadIdx.x;
    const int b0  = blockIdx.x * 2;

    // ---- init: x0, u0 into parity-0 buffer ----
    if (tid < 128) {
        int e = tid >> 6, j = tid & 63;
        sxu[0][e][j] = x0[(size_t)(b0 + e) * NXX + j];
    } else if (tid < 192) {
        int q = tid - 128;
        int e = q >> 5, k = q & 31;
        sxu[0][e][64 + k] = u[(size_t)(b0 + e) * TT * NUU + k];
    }

    if (tid < 128) {
        // ===================== GEMV1 warps =====================
        const int h = tid;
        float wg1r[96];
        float wh1r[64];
        #pragma unroll
        for (int k = 0; k < 96; k++) wg1r[k] = Wg1[k * HH + h];
        #pragma unroll
        for (int k = 0; k < 64; k++) wh1r[k] = Wh1[k * HH + h];
        const float bg1r = bg1[h];
        const float bh1r = bh1[h];

        __syncthreads();  // init visible

        #pragma unroll 1
        for (int t = 0; t < TT; t++) {
            const int p = t & 1;
            const float4* x40 = (const float4*)&sxu[p][0][0];
            const float4* x41 = (const float4*)&sxu[p][1][0];

            // ---- phase 1: g-net layer 1 (k = 0..95 ascending) ----
            float zg0 = 0.f, zg1 = 0.f;
            #pragma unroll
            for (int k4 = 0; k4 < 24; k4++) {
                const float4 a = x40[k4];
                const float4 b = x41[k4];
                zg0 = fmaf(a.x, wg1r[4*k4+0], zg0);
                zg0 = fmaf(a.y, wg1r[4*k4+1], zg0);
                zg0 = fmaf(a.z, wg1r[4*k4+2], zg0);
                zg0 = fmaf(a.w, wg1r[4*k4+3], zg0);
                zg1 = fmaf(b.x, wg1r[4*k4+0], zg1);
                zg1 = fmaf(b.y, wg1r[4*k4+1], zg1);
                zg1 = fmaf(b.z, wg1r[4*k4+2], zg1);
                zg1 = fmaf(b.w, wg1r[4*k4+3], zg1);
            }
            g1s[0][h] = xla_tanh(__fadd_rn(zg0, bg1r));
            g1s[1][h] = xla_tanh(__fadd_rn(zg1, bg1r));
            __syncthreads();  // A: g1 published -> dx chain may start

            // ---- phase 2 (overlaps dx chain): h-net layer 1 ----
            float zh0 = 0.f, zh1 = 0.f;
            #pragma unroll
            for (int k4 = 0; k4 < 16; k4++) {
                const float4 a = x40[k4];
                const float4 b = x41[k4];
                zh0 = fmaf(a.x, wh1r[4*k4+0], zh0);
                zh0 = fmaf(a.y, wh1r[4*k4+1], zh0);
                zh0 = fmaf(a.z, wh1r[4*k4+2], zh0);
                zh0 = fmaf(a.w, wh1r[4*k4+3], zh0);
                zh1 = fmaf(b.x, wh1r[4*k4+0], zh1);
                zh1 = fmaf(b.y, wh1r[4*k4+1], zh1);
                zh1 = fmaf(b.z, wh1r[4*k4+2], zh1);
                zh1 = fmaf(b.w, wh1r[4*k4+3], zh1);
            }
            h1p[p][0][h] = xla_tanh(__fadd_rn(zh0, bh1r));
            h1p[p][1][h] = xla_tanh(__fadd_rn(zh1, bh1r));
            __syncthreads();  // B: state + h1 committed
        }
    } else if (tid < 256) {
        // ===================== dx warps =====================
        const int q = tid - 128;
        const int e = q >> 6;
        const int j = q & 63;

        float wg2r[128];
        #pragma unroll
        for (int i = 0; i < 128; i++) wg2r[i] = Wg2[i * NXX + j];
        const float bg2r = bg2[j];

        const size_t ox_base = (size_t)(b0 + e) * TT * NXX + j;
        const int eu = q >> 5, ku = q & 31;              // u prefetch duty (q<64)
        const size_t u_base = (size_t)(b0 + eu) * TT * NUU + ku;

        float xreg = x0[(size_t)(b0 + e) * NXX + j];     // x_t in register

        __syncthreads();  // init visible

        const float4* g4 = (const float4*)&g1s[e][0];

        #pragma unroll 1
        for (int t = 0; t < TT; t++) {
            const int pn = (t + 1) & 1;

            // ---- phase 1: record x_t, launch u(t+1) load ----
            out_x[ox_base + (size_t)t * NXX] = xreg;
            float un = 0.0f;
            if (q < 64) {
                int tn = (t + 1 < TT) ? (t + 1) : (TT - 1);
                un = u[u_base + (size_t)tn * NUU];
            }
            __syncthreads();  // A: g1 ready

            // ---- phase 2: sequential 128-dot (ascending i) ----
            float dxa = 0.0f;
            #pragma unroll
            for (int i4 = 0; i4 < 32; i4++) {
                const float4 v = g4[i4];
                dxa = fmaf(v.x, wg2r[4*i4+0], dxa);
                dxa = fmaf(v.y, wg2r[4*i4+1], dxa);
                dxa = fmaf(v.z, wg2r[4*i4+2], dxa);
                dxa = fmaf(v.w, wg2r[4*i4+3], dxa);
            }
            // pinned HLO order: x_{t+1} = x + (dot + bg2)
            xreg = __fadd_rn(xreg, __fadd_rn(dxa, bg2r));
            sxu[pn][e][j] = xreg;
            if (q < 64) sxu[pn][eu][64 + ku] = un;
            __syncthreads();  // B
        }
    } else {
        // ===================== y warp (one step behind) =====================
        const int o  = tid - 256;       // 0..31
        const int e  = o >> 4;
        const int oo = o & 15;

        float wh2r[128];
        #pragma unroll
        for (int i = 0; i < 128; i++) wh2r[i] = Wh2[i * NYY + oo];
        const float bh2r = bh2[oo];

        const size_t oy_base = (size_t)(b0 + e) * TT * NYY + oo;

        __syncthreads();  // init visible

        #pragma unroll 1
        for (int t = 0; t < TT; t++) {
            // ---- phase 1: compute y(t-1) from h1p[(t-1)&1] ----
            if (t > 0) {
                const int pp = (t - 1) & 1;
                const float4* h4 = (const float4*)&h1p[pp][e][0];
                float ya = 0.0f;
                #pragma unroll
                for (int i4 = 0; i4 < 32; i4++) {
                    const float4 v = h4[i4];
                    ya = fmaf(v.x, wh2r[4*i4+0], ya);
                    ya = fmaf(v.y, wh2r[4*i4+1], ya);
                    ya = fmaf(v.z, wh2r[4*i4+2], ya);
                    ya = fmaf(v.w, wh2r[4*i4+3], ya);
                }
                out_y[oy_base + (size_t)(t - 1) * NYY] = __fadd_rn(ya, bh2r);
            }
            __syncthreads();  // A
            __syncthreads();  // B
        }
        // drain: y(TT-1)
        {
            const int pp = (TT - 1) & 1;
            const float4* h4 = (const float4*)&h1p[pp][e][0];
            float ya = 0.0f;
            #pragma unroll
            for (int i4 = 0; i4 < 32; i4++) {
                const float4 v = h4[i4];
                ya = fmaf(v.x, wh2r[4*i4+0], ya);
                ya = fmaf(v.y, wh2r[4*i4+1], ya);
                ya = fmaf(v.z, wh2r[4*i4+2], ya);
                ya = fmaf(v.w, wh2r[4*i4+3], ya);
            }
            out_y[oy_base + (size_t)(TT - 1) * NYY] = __fadd_rn(ya, bh2r);
        }
    }
}

extern "C" void kernel_launch(void* const* d_in, const int* in_sizes, int n_in,
                              void* d_out, int out_size)
{
    const float* x0  = (const float*)d_in[0];
    const float* u   = (const float*)d_in[1];
    const float* Wg1 = (const float*)d_in[2];
    const float* bg1 = (const float*)d_in[3];
    const float* Wg2 = (const float*)d_in[4];
    const float* bg2 = (const float*)d_in[5];
    const float* Wh1 = (const float*)d_in[6];
    const float* bh1 = (const float*)d_in[7];
    const float* Wh2 = (const float*)d_in[8];
    const float* bh2 = (const float*)d_in[9];

    float* out_x = (float*)d_out;
    float* out_y = out_x + (size_t)BB * TT * NXX;

    ssm_kernel<<<BB / 2, 288>>>(x0, u, Wg1, bg1, Wg2, bg2,
                                Wh1, bh1, Wh2, bh2, out_x, out_y);
}